// round 11
// baseline (speedup 1.0000x reference)
#include <cuda_runtime.h>

// Problem constants
#define BB 16
#define WW 8192
#define FF 256
#define F4 64              // FF / 4 (float4 lanes per row)
#define OW (2*WW - 1)      // 16383 output rows per (b, 1)
#define RPT 8              // input rows per thread
#define GROUPS 4           // row-groups per block (blockDim = GROUPS*64 = 256)
#define ROWS_PER_BLOCK (RPT * GROUPS)   // 32

__global__ __launch_bounds__(256)
void learning_upsampler_kernel(const float4* __restrict__ x,
                               const float*  __restrict__ w0,
                               float4* __restrict__ out)
{
    const int f4  = threadIdx.x & 63;       // float4 lane within feature dim
    const int grp = threadIdx.x >> 6;       // row-group within block

    const int blocks_per_batch = WW / ROWS_PER_BLOCK;   // 256
    const int b    = blockIdx.x / blocks_per_batch;
    const int blk  = blockIdx.x % blocks_per_batch;
    const int row0 = blk * ROWS_PER_BLOCK + grp * RPT;

    // Per-thread blend weights: w = sigmoid(weights0[f]), for the 4 features
    // this lane owns. Computed once per thread; cost is negligible vs HBM.
    float w[4], mw[4];
    #pragma unroll
    for (int j = 0; j < 4; j++) {
        float v = w0[f4 * 4 + j];
        float s = 1.0f / (1.0f + __expf(-v));
        w[j]  = s;
        mw[j] = 1.0f - s;
    }

    const float4* xb = x   + (size_t)b * WW * F4;
    float4*       ob = out + (size_t)b * OW * F4;

    // Walk RPT consecutive input rows, carrying x[row+1] in a register so
    // each input element is loaded once per thread (9 loads / 8 rows).
    float4 cur = xb[(size_t)row0 * F4 + f4];

    #pragma unroll
    for (int r = 0; r < RPT; r++) {
        const int row = row0 + r;

        // even output row 2*row = original x row
        ob[(size_t)(2 * row) * F4 + f4] = cur;

        if (row + 1 < WW) {
            float4 nxt = xb[(size_t)(row + 1) * F4 + f4];
            float4 o;
            o.x = fmaf(w[0], cur.x, mw[0] * nxt.x);
            o.y = fmaf(w[1], cur.y, mw[1] * nxt.y);
            o.z = fmaf(w[2], cur.z, mw[2] * nxt.z);
            o.w = fmaf(w[3], cur.w, mw[3] * nxt.w);
            // odd output row 2*row+1 = blend of x[row], x[row+1]
            ob[(size_t)(2 * row + 1) * F4 + f4] = o;
            cur = nxt;
        }
    }
}

extern "C" void kernel_launch(void* const* d_in, const int* in_sizes, int n_in,
                              void* d_out, int out_size)
{
    const float4* x  = (const float4*)d_in[0];   // [16,1,8192,256] fp32
    const float*  w0 = (const float*) d_in[1];   // [256] fp32
    float4*       o  = (float4*)d_out;           // [16,1,16383,256] fp32

    const int blocks_per_batch = WW / ROWS_PER_BLOCK;     // 256
    dim3 grid(BB * blocks_per_batch);                     // 4096 blocks
    dim3 block(256);
    learning_upsampler_kernel<<<grid, block>>>(x, w0, o);
}